// round 15
// baseline (speedup 1.0000x reference)
#include <cuda_runtime.h>
#include <cuda_fp16.h>
#include <cstdint>
#include <cstddef>

#define SLEN   4096
#define BATCH  2
#define DMODEL 768
#define NHEADS 12
#define HDIM   64
#define MROWS  (BATCH * SLEN)   // 8192
#define NQKV   (3 * DMODEL)     // 2304

// ---------------- scratch (__device__ globals) -----------------------------
__device__ __half g_xh[(size_t)MROWS * DMODEL];
__device__ __half g_wqkvh[(size_t)DMODEL * NQKV];   // [N][K]
__device__ __half g_wouth[(size_t)DMODEL * DMODEL]; // [N][K]
__device__ __half g_qkvh[(size_t)MROWS * NQKV];     // fp16 Q|K|V
__device__ __half g_ctxh[(size_t)MROWS * DMODEL];

// ---------------- helpers --------------------------------------------------
__device__ __forceinline__ uint32_t s2u(const void* p) {
    return (uint32_t)__cvta_generic_to_shared(p);
}
__device__ __forceinline__ uint32_t swz(uint32_t b) {           // SW128
    return b ^ ((b >> 3) & 0x70);
}
__device__ __forceinline__ void ldsm4(uint32_t r[4], uint32_t addr) {
    asm volatile("ldmatrix.sync.aligned.m8n8.x4.shared.b16 {%0,%1,%2,%3}, [%4];"
                 : "=r"(r[0]), "=r"(r[1]), "=r"(r[2]), "=r"(r[3]) : "r"(addr));
}
__device__ __forceinline__ void ldsm4t(uint32_t r[4], uint32_t addr) {
    asm volatile("ldmatrix.sync.aligned.m8n8.x4.trans.shared.b16 {%0,%1,%2,%3}, [%4];"
                 : "=r"(r[0]), "=r"(r[1]), "=r"(r[2]), "=r"(r[3]) : "r"(addr));
}
__device__ __forceinline__ void cp16(uint32_t dst, const void* src) {
    asm volatile("cp.async.cg.shared.global [%0], [%1], 16;" :: "r"(dst), "l"(src));
}
__device__ __forceinline__ void mma_f16(float c[4], const uint32_t a[4],
                                        const uint32_t b[2]) {
    asm volatile(
        "mma.sync.aligned.m16n8k16.row.col.f32.f16.f16.f32 "
        "{%0,%1,%2,%3}, {%4,%5,%6,%7}, {%8,%9}, {%0,%1,%2,%3};\n"
        : "+f"(c[0]), "+f"(c[1]), "+f"(c[2]), "+f"(c[3])
        : "r"(a[0]), "r"(a[1]), "r"(a[2]), "r"(a[3]), "r"(b[0]), "r"(b[1]));
}
__device__ __forceinline__ unsigned pack2(float x, float y) {
    __half2 h = __floats2half2_rn(x, y);
    return *reinterpret_cast<unsigned*>(&h);
}
// 2^x on a packed half2 pair (inputs given as two floats)
__device__ __forceinline__ uint32_t ex2h2(float x, float y) {
    uint32_t h = pack2(x, y);
    uint32_t r;
    asm("ex2.approx.f16x2 %0, %1;" : "=r"(r) : "r"(h));
    return r;
}

// ---------------- converts -------------------------------------------------
__global__ void to_half(const float* __restrict__ src, __half* __restrict__ dst, int n4) {
    int i = blockIdx.x * blockDim.x + threadIdx.x;
    int stride = gridDim.x * blockDim.x;
    for (; i < n4; i += stride) {
        float4 v = reinterpret_cast<const float4*>(src)[i];
        reinterpret_cast<__half2*>(dst)[2 * i]     = __floats2half2_rn(v.x, v.y);
        reinterpret_cast<__half2*>(dst)[2 * i + 1] = __floats2half2_rn(v.z, v.w);
    }
}

// W[K][N] fp32 -> WT[N][K] fp16 (transpose + convert)
__global__ void conv_wT(const float* __restrict__ W, __half* __restrict__ WT,
                        int K, int N) {
    __shared__ float t[32][33];
    const int k0 = blockIdx.y * 32, n0 = blockIdx.x * 32;
    const int tx = threadIdx.x & 31, ty = threadIdx.x >> 5;
#pragma unroll
    for (int m = 0; m < 4; m++)
        t[ty + 8 * m][tx] = W[(size_t)(k0 + ty + 8 * m) * N + n0 + tx];
    __syncthreads();
#pragma unroll
    for (int m = 0; m < 4; m++)
        WT[(size_t)(n0 + ty + 8 * m) * K + k0 + tx] = __float2half_rn(t[tx][ty + 8 * m]);
}

// ---------------- 1-pass fp16 GEMM, BM=128 (QKV; proven) -------------------
#define GBUF 32768   // bytes per buffer (A 16K + B 16K)
__global__ __launch_bounds__(256, 2)
void hgemm128(const __half* __restrict__ A, const __half* __restrict__ Bt,
              __half* __restrict__ Ch, int M, int N, int K) {
    extern __shared__ __half sm[];
    const int tid = threadIdx.x, lane = tid & 31, w = tid >> 5;
    const int gid = lane >> 2, tig = lane & 3;
    const int wm = (w >> 2) * 64, wn = (w & 3) * 32;
    const int bm = blockIdx.y * 128, bn = blockIdx.x * 128;
    const uint32_t sb = s2u(sm);

    float acc[4][4][4];
#pragma unroll
    for (int i = 0; i < 4; i++)
#pragma unroll
        for (int j = 0; j < 4; j++)
#pragma unroll
            for (int e = 0; e < 4; e++) acc[i][j][e] = 0.f;

    const int nit = K >> 6;

#define G_LOAD(k0, buf)                                                         \
    {                                                                           \
        uint32_t bb = sb + (uint32_t)(buf) * GBUF;                              \
        _Pragma("unroll")                                                       \
        for (int p = 0; p < 4; p++) {                                           \
            int id = tid + p * 256;                                             \
            int row = id >> 3, chB = (id & 7) << 4;                             \
            uint32_t so = swz((uint32_t)(row * 128 + chB));                     \
            cp16(bb + so,                                                       \
                 (const char*)(A + (size_t)(bm + row) * K + (k0)) + chB);       \
            cp16(bb + 16384 + so,                                               \
                 (const char*)(Bt + (size_t)(bn + row) * K + (k0)) + chB);      \
        }                                                                       \
        asm volatile("cp.async.commit_group;" ::: "memory");                    \
    }

    G_LOAD(0, 0);

    const int arow  = lane & 15;
    const int acolB = ((lane >> 4) << 3) * 2;
    const int brow  = ((lane >> 4) << 3) + (lane & 7);
    const int bcolB = (((lane >> 3) & 1) << 3) * 2;

    for (int it = 0; it < nit; it++) {
        asm volatile("cp.async.wait_group 0;" ::: "memory");
        __syncthreads();
        if (it + 1 < nit) G_LOAD((it + 1) << 6, (it + 1) & 1);

        uint32_t aB = sb + (uint32_t)(it & 1) * GBUF;
        uint32_t bB = aB + 16384;
#pragma unroll
        for (int kk = 0; kk < 64; kk += 16) {
            uint32_t af[4][4];
#pragma unroll
            for (int i = 0; i < 4; i++)
                ldsm4(af[i], aB + swz((uint32_t)((wm + 16 * i + arow) * 128 +
                                                 kk * 2 + acolB)));
#pragma unroll
            for (int jp = 0; jp < 2; jp++) {
                uint32_t bh[4];
                ldsm4(bh, bB + swz((uint32_t)((wn + 16 * jp + brow) * 128 +
                                              kk * 2 + bcolB)));
#pragma unroll
                for (int i = 0; i < 4; i++) {
                    mma_f16(acc[i][2 * jp],     af[i], &bh[0]);
                    mma_f16(acc[i][2 * jp + 1], af[i], &bh[2]);
                }
            }
        }
        __syncthreads();
    }

#pragma unroll
    for (int i = 0; i < 4; i++)
#pragma unroll
        for (int j = 0; j < 4; j++) {
            int r0 = bm + wm + i * 16 + gid;
            int cc = bn + wn + j * 8 + 2 * tig;
            *(__half2*)(Ch + (size_t)r0 * N + cc) =
                __floats2half2_rn(acc[i][j][0], acc[i][j][1]);
            *(__half2*)(Ch + (size_t)(r0 + 8) * N + cc) =
                __floats2half2_rn(acc[i][j][2], acc[i][j][3]);
        }
}

// ---------------- BM=64 fp16 GEMM (out-proj; proven R14) -------------------
#define GBUF64 24576   // A 8K + B 16K
__global__ __launch_bounds__(256, 2)
void hgemm64(const __half* __restrict__ A, const __half* __restrict__ Bt,
             float* __restrict__ Cf, int M, int N, int K) {
    extern __shared__ __half sm[];
    const int tid = threadIdx.x, lane = tid & 31, w = tid >> 5;
    const int gid = lane >> 2, tig = lane & 3;
    const int wm = (w >> 2) * 32, wn = (w & 3) * 32;
    const int bm = blockIdx.y * 64, bn = blockIdx.x * 128;
    const uint32_t sb = s2u(sm);

    float acc[2][4][4];
#pragma unroll
    for (int i = 0; i < 2; i++)
#pragma unroll
        for (int j = 0; j < 4; j++)
#pragma unroll
            for (int e = 0; e < 4; e++) acc[i][j][e] = 0.f;

    const int nit = K >> 6;

#define G_LOAD64(k0, buf)                                                       \
    {                                                                           \
        uint32_t bb = sb + (uint32_t)(buf) * GBUF64;                            \
        _Pragma("unroll")                                                       \
        for (int p = 0; p < 2; p++) {                                           \
            int id = tid + p * 256;                                             \
            int row = id >> 3, chB = (id & 7) << 4;                             \
            uint32_t so = swz((uint32_t)(row * 128 + chB));                     \
            cp16(bb + so,                                                       \
                 (const char*)(A + (size_t)(bm + row) * K + (k0)) + chB);       \
        }                                                                       \
        _Pragma("unroll")                                                       \
        for (int p = 0; p < 4; p++) {                                           \
            int id = tid + p * 256;                                             \
            int row = id >> 3, chB = (id & 7) << 4;                             \
            uint32_t so = swz((uint32_t)(row * 128 + chB));                     \
            cp16(bb + 8192 + so,                                                \
                 (const char*)(Bt + (size_t)(bn + row) * K + (k0)) + chB);      \
        }                                                                       \
        asm volatile("cp.async.commit_group;" ::: "memory");                    \
    }

    G_LOAD64(0, 0);

    const int arow  = lane & 15;
    const int acolB = ((lane >> 4) << 3) * 2;
    const int brow  = ((lane >> 4) << 3) + (lane & 7);
    const int bcolB = (((lane >> 3) & 1) << 3) * 2;

    for (int it = 0; it < nit; it++) {
        asm volatile("cp.async.wait_group 0;" ::: "memory");
        __syncthreads();
        if (it + 1 < nit) G_LOAD64((it + 1) << 6, (it + 1) & 1);

        uint32_t aB = sb + (uint32_t)(it & 1) * GBUF64;
        uint32_t bB = aB + 8192;
#pragma unroll
        for (int kk = 0; kk < 64; kk += 16) {
            uint32_t af[2][4];
#pragma unroll
            for (int i = 0; i < 2; i++)
                ldsm4(af[i], aB + swz((uint32_t)((wm + 16 * i + arow) * 128 +
                                                 kk * 2 + acolB)));
#pragma unroll
            for (int jp = 0; jp < 2; jp++) {
                uint32_t bh[4];
                ldsm4(bh, bB + swz((uint32_t)((wn + 16 * jp + brow) * 128 +
                                              kk * 2 + bcolB)));
#pragma unroll
                for (int i = 0; i < 2; i++) {
                    mma_f16(acc[i][2 * jp],     af[i], &bh[0]);
                    mma_f16(acc[i][2 * jp + 1], af[i], &bh[2]);
                }
            }
        }
        __syncthreads();
    }

#pragma unroll
    for (int i = 0; i < 2; i++)
#pragma unroll
        for (int j = 0; j < 4; j++) {
            int r0 = bm + wm + i * 16 + gid;
            int cc = bn + wn + j * 8 + 2 * tig;
            *(float2*)(Cf + (size_t)r0 * N + cc) =
                make_float2(acc[i][j][0], acc[i][j][1]);
            *(float2*)(Cf + (size_t)(r0 + 8) * N + cc) =
                make_float2(acc[i][j][2], acc[i][j][3]);
        }
}

// ---------------- fp16 flash attention, software-pipelined -----------------
// Static-max softmax (p = 2^s), l via ones-MMA. PV of tile t-1 interleaved
// with S of tile t inside each iteration (breaks the phase convoy); the pa
// fragment array is the pipeline register (consumed before overwritten per
// j-half). Triple-buffered KV so one barrier/tile covers buffer reuse.
// dyn smem bytes: Q @0 (16K); KV buf i at 16384+i*16384 (K 8K | V 8K)
#define ATT_QB   16384
#define ATT_KVB  16384
#define ATT_SMEM 65536
__global__ __launch_bounds__(256, 2)
void attn_mma() {
    extern __shared__ __half asm_[];
    const uint32_t sb = s2u(asm_);
    const int tid  = threadIdx.x;
    const int lane = tid & 31;
    const int w    = tid >> 5;
    const int gid  = lane >> 2;
    const int tig  = lane & 3;
    // Reverse order: heaviest q-tiles launch first.
    const int qt = gridDim.x - 1 - blockIdx.x;
    const int h = blockIdx.y, b = blockIdx.z;
    const int qbase = qt * 128;
    const size_t rowb = (size_t)b * SLEN;
    // Q pre-scale: (1/8) * log2(e) -> logits in log2 domain.
    const __half2 qscale = __floats2half2_rn(0.18033688f, 0.18033688f);

    // Load Q tile (128 rows x 64 halves = 128B rows), swizzled 8B stores
#pragma unroll
    for (int t = 0; t < 8; t++) {
        int c = tid + t * 256;
        int r = c >> 4, dc = (c & 15) << 2;
        uint2 v = *(const uint2*)(g_qkvh + (rowb + qbase + r) * NQKV + h * HDIM + dc);
        __half2 v0 = __hmul2(*reinterpret_cast<__half2*>(&v.x), qscale);
        __half2 v1 = __hmul2(*reinterpret_cast<__half2*>(&v.y), qscale);
        uint2 pkd = make_uint2(*(uint32_t*)&v0, *(uint32_t*)&v1);
        *(uint2*)((char*)asm_ + swz((uint32_t)(r * 128 + dc * 2))) = pkd;
    }

#define KV_LOAD(kb_, buf_)                                                         \
    {                                                                              \
        _Pragma("unroll")                                                          \
        for (int p = 0; p < 2; p++) {                                              \
            int id = tid + p * 256;                                                \
            int r = id >> 3, chB = (id & 7) << 4;                                  \
            uint32_t so = swz((uint32_t)(r * 128 + chB));                          \
            uint32_t bbase = sb + ATT_QB + (uint32_t)(buf_) * ATT_KVB;             \
            cp16(bbase + so,                                                       \
                 (const char*)(g_qkvh + (rowb + (kb_) + r) * NQKV + DMODEL +       \
                               h * HDIM) + chB);                                   \
            cp16(bbase + 8192 + so,                                                \
                 (const char*)(g_qkvh + (rowb + (kb_) + r) * NQKV + 2 * DMODEL +   \
                               h * HDIM) + chB);                                   \
        }                                                                          \
        asm volatile("cp.async.commit_group;" ::: "memory");                       \
    }

// S j-half hf of the tile whose K buffer base is kB_ -> s[4][4]
#define S_HALF(kB_, hf)                                                            \
    _Pragma("unroll")                                                              \
    for (int kk4 = 0; kk4 < 4; kk4++) {                                            \
        _Pragma("unroll")                                                          \
        for (int jp2 = 0; jp2 < 2; jp2++) {                                        \
            const int jp = 2 * (hf) + jp2;                                         \
            uint32_t bk[4];                                                        \
            ldsm4(bk, (kB_) + swz((uint32_t)((jp * 16 + brow) * 128 +              \
                                             kk4 * 32 + bcolB)));                  \
            mma_f16(s[2 * jp2],     aq[kk4], &bk[0]);                              \
            mma_f16(s[2 * jp2 + 1], aq[kk4], &bk[2]);                              \
        }                                                                          \
    }

// PV + l for one kc chunk using pa[kc] against V buffer base vB_
#define PV_KC(vB_, kc)                                                             \
    {                                                                              \
        mma_f16(lacc, pa[kc], onesb);                                              \
        _Pragma("unroll")                                                          \
        for (int jp = 0; jp < 4; jp++) {                                           \
            uint32_t bv[4];                                                        \
            ldsm4t(bv, (vB_) + swz((uint32_t)(((kc) * 16 + vrow) * 128 +           \
                                              jp * 32 + vcolB)));                  \
            mma_f16(o[2 * jp],     pa[kc], &bv[0]);                                \
            mma_f16(o[2 * jp + 1], pa[kc], &bv[2]);                                \
        }                                                                          \
    }

// mask j-half hf of tile at key base kb_ (only when diagonal-crossing)
#define MASK_HALF(kb_, hf)                                                         \
    _Pragma("unroll")                                                              \
    for (int j = 0; j < 4; j++) {                                                  \
        int c0 = (kb_) + 8 * (4 * (hf) + j) + 2 * tig;                             \
        if (c0 > row0)     s[j][0] = -30000.f;                                     \
        if (c0 + 1 > row0) s[j][1] = -30000.f;                                     \
        if (c0 > row1)     s[j][2] = -30000.f;                                     \
        if (c0 + 1 > row1) s[j][3] = -30000.f;                                     \
    }

// ex2 j-half hf -> pa[2hf], pa[2hf+1]
#define EX2_HALF(hf)                                                               \
    _Pragma("unroll")                                                              \
    for (int c = 0; c < 2; c++) {                                                  \
        const int kc = 2 * (hf) + c;                                               \
        pa[kc][0] = ex2h2(s[2 * c][0],     s[2 * c][1]);                           \
        pa[kc][1] = ex2h2(s[2 * c][2],     s[2 * c][3]);                           \
        pa[kc][2] = ex2h2(s[2 * c + 1][0], s[2 * c + 1][1]);                       \
        pa[kc][3] = ex2h2(s[2 * c + 1][2], s[2 * c + 1][3]);                       \
    }

    float o[8][4];
#pragma unroll
    for (int j = 0; j < 8; j++)
#pragma unroll
        for (int e = 0; e < 4; e++) o[j][e] = 0.f;
    float lacc[4] = {0.f, 0.f, 0.f, 0.f};
    const uint32_t onesb[2] = {0x3C003C00u, 0x3C003C00u};

    const int arow  = lane & 15;
    const int acolB = ((lane >> 4) << 3) * 2;
    const int brow  = ((lane >> 4) << 3) + (lane & 7);
    const int bcolB = (((lane >> 3) & 1) << 3) * 2;
    const int vrow  = (lane & 7) + (((lane >> 3) & 1) << 3);
    const int vcolB = (lane >> 4) << 4;
    const int row0 = qbase + w * 16 + gid;
    const int row1 = row0 + 8;

    const int nkt = 2 * qt + 2;
    KV_LOAD(0, 0);
    asm volatile("cp.async.wait_group 0;" ::: "memory");
    __syncthreads();                      // Q + KV0 visible

    // Hoist Q fragments into registers
    uint32_t aq[4][4];
#pragma unroll
    for (int kk4 = 0; kk4 < 4; kk4++)
        ldsm4(aq[kk4], sb + swz((uint32_t)((w * 16 + arow) * 128 +
                                           kk4 * 32 + acolB)));

    KV_LOAD(64, 1);                       // nkt >= 2 always

    uint32_t pa[4][4];
    // ---- prologue: S(0) -> pa (no PV yet) ----
    {
        const uint32_t kB = sb + ATT_QB;
        const bool diag = (0 + 63 > row0);
#pragma unroll
        for (int hf = 0; hf < 2; hf++) {
            float s[4][4];
#pragma unroll
            for (int j = 0; j < 4; j++)
#pragma unroll
                for (int e = 0; e < 4; e++) s[j][e] = 0.f;
            S_HALF(kB, hf)
            if (diag) { MASK_HALF(0, hf) }
            EX2_HALF(hf)
        }
    }

    // ---- pipelined mainloop: PV(t-1) interleaved with S(t) ----
    for (int t = 1; t < nkt; t++) {
        asm volatile("cp.async.wait_group 0;" ::: "memory");
        __syncthreads();                  // KV(t) visible; buf (t+1)%3 free
        if (t + 1 < nkt) {
            int nb = t + 1; nb -= (nb / 3) * 3;
            KV_LOAD((t + 1) * 64, nb);
        }
        int cb = t; cb -= (cb / 3) * 3;
        int pb = t - 1; pb -= (pb / 3) * 3;
        const uint32_t kB = sb + ATT_QB + (uint32_t)cb * ATT_KVB;
        const uint32_t vB = sb + ATT_QB + (uint32_t)pb * ATT_KVB + 8192;
        const int kb = t * 64;
        const bool diag = (kb + 63 > row0);

#pragma unroll
        for (int hf = 0; hf < 2; hf++) {
            float s[4][4];
#pragma unroll
            for (int j = 0; j < 4; j++)
#pragma unroll
                for (int e = 0; e < 4; e++) s[j][e] = 0.f;
            // independent streams: S(t) j-half and PV(t-1) kc pair —
            // ptxas interleaves them, keeping tensor + MUFU pipes co-busy
            S_HALF(kB, hf)
            PV_KC(vB, 2 * hf)
            PV_KC(vB, 2 * hf + 1)
            if (diag) { MASK_HALF(kb, hf) }
            EX2_HALF(hf)                  // overwrites consumed pa slots
        }
    }

    // ---- epilogue: PV for the last tile ----
    {
        int pb = nkt - 1; pb -= (pb / 3) * 3;
        const uint32_t vB = sb + ATT_QB + (uint32_t)pb * ATT_KVB + 8192;
        PV_KC(vB, 0)
        PV_KC(vB, 1)
        PV_KC(vB, 2)
        PV_KC(vB, 3)
    }

    // normalize, store fp16 ctx  (lacc[0] = row0 sum, lacc[2] = row1 sum)
    const float inv0 = 1.f / lacc[0], inv1 = 1.f / lacc[2];
    const size_t r0g = rowb + qbase + w * 16 + gid;
#pragma unroll
    for (int j = 0; j < 8; j++) {
        int col = h * HDIM + 8 * j + 2 * tig;
        *(__half2*)(g_ctxh + r0g * DMODEL + col) =
            __floats2half2_rn(o[j][0] * inv0, o[j][1] * inv0);
        *(__half2*)(g_ctxh + (r0g + 8) * DMODEL + col) =
            __floats2half2_rn(o[j][2] * inv1, o[j][3] * inv1);
    }
}

// ---------------------------------------------------------------------------
extern "C" void kernel_launch(void* const* d_in, const int* in_sizes, int n_in,
                              void* d_out, int out_size) {
    const float* x     = (const float*)d_in[0];
    const float* w_qkv = (const float*)d_in[1];
    const float* w_out = (const float*)d_in[2];
    float* out = (float*)d_out;

    __half *xh, *wqh, *woh, *qkvh, *ctxh;
    cudaGetSymbolAddress((void**)&xh,   g_xh);
    cudaGetSymbolAddress((void**)&wqh,  g_wqkvh);
    cudaGetSymbolAddress((void**)&woh,  g_wouth);
    cudaGetSymbolAddress((void**)&qkvh, g_qkvh);
    cudaGetSymbolAddress((void**)&ctxh, g_ctxh);

    const int smemG128 = 2 * GBUF;    // 65536 B
    const int smemG64  = 2 * GBUF64;  // 49152 B
    cudaFuncSetAttribute(hgemm128,
                         cudaFuncAttributeMaxDynamicSharedMemorySize, smemG128);
    cudaFuncSetAttribute(hgemm64,
                         cudaFuncAttributeMaxDynamicSharedMemorySize, smemG64);
    cudaFuncSetAttribute(attn_mma,
                         cudaFuncAttributeMaxDynamicSharedMemorySize, ATT_SMEM);

    to_half<<<256, 256>>>(x, xh, MROWS * DMODEL / 4);
    conv_wT<<<dim3(NQKV / 32, DMODEL / 32), 256>>>(w_qkv, wqh, DMODEL, NQKV);
    conv_wT<<<dim3(DMODEL / 32, DMODEL / 32), 256>>>(w_out, woh, DMODEL, DMODEL);

    // QKV projection (fp16 out): [8192,768] @ [768,2304]
    hgemm128<<<dim3(NQKV / 128, MROWS / 128), 256, smemG128>>>(
        xh, wqh, qkvh, MROWS, NQKV, DMODEL);

    // causal attention -> ctx (software-pipelined)
    attn_mma<<<dim3(SLEN / 128, NHEADS, BATCH), 256, ATT_SMEM>>>();

    // output projection (fp32 out): [8192,768] @ [768,768], BM=64 for tail
    hgemm64<<<dim3(DMODEL / 128, MROWS / 64), 256, smemG64>>>(
        ctxh, woh, out, MROWS, DMODEL, DMODEL);
}